// round 2
// baseline (speedup 1.0000x reference)
#include <cuda_runtime.h>
#include <cuda_bf16.h>
#include <mma.h>

using namespace nvcuda;

// ---------------------------------------------------------------------------
// Problem constants
// ---------------------------------------------------------------------------
#define H 64
#define NNODES 40000
#define NE 60000
#define NC5 30000
#define NC6 25000
#define E_ROWS (2 * NE)      // 120000
#define C5_ROWS (5 * NC5)    // 150000
#define C6_ROWS (6 * NC6)    // 150000
#define EPS 1e-5f
#define PAD_ROWS 128         // GEMM stores are unguarded; pad scratch outputs

// ---------------------------------------------------------------------------
// Device scratch (static: no allocation allowed)
// ---------------------------------------------------------------------------
__device__ float g_node64[NNODES * 64];
__device__ float g_node128[NNODES * 128];
__device__ float g_nodeS[NNODES * 320];
__device__ float g_tmp128[C5_ROWS * 128];
__device__ float g_new5[C5_ROWS * 320];
__device__ float g_new6[C6_ROWS * 320];
__device__ float g_xE[E_ROWS * 704];
__device__ float g_h[(C5_ROWS + PAD_ROWS) * 128];   // GEMM1 out (padded)
__device__ float g_z[(C5_ROWS + PAD_ROWS) * 64];    // GEMM2 out (padded)
__device__ float g_sum[128];
__device__ float g_sq[128];
__device__ float g_scale1[128];
__device__ float g_shift1[128];
__device__ float g_scale2[64];
__device__ float g_shift2[64];

// ---------------------------------------------------------------------------
// Utility kernels
// ---------------------------------------------------------------------------
__global__ void zero_kernel(float* __restrict__ p, size_t n) {
    size_t i = (size_t)blockIdx.x * blockDim.x + threadIdx.x;
    if (i < n) p[i] = 0.f;
}

__global__ void scatter_add4(const float* __restrict__ src,
                             const int* __restrict__ atoms,
                             float* __restrict__ node, int rows, int C) {
    int C4 = C >> 2;
    int idx = blockIdx.x * blockDim.x + threadIdx.x;
    int total = rows * C4;
    if (idx >= total) return;
    int r = idx / C4;
    int c = (idx - r * C4) << 2;
    float4 v = *reinterpret_cast<const float4*>(&src[(size_t)r * C + c]);
    float* dst = &node[(size_t)atoms[r] * C + c];
    atomicAdd(dst + 0, v.x);
    atomicAdd(dst + 1, v.y);
    atomicAdd(dst + 2, v.z);
    atomicAdd(dst + 3, v.w);
}

template <int G>
__global__ void gather_lb(const float* __restrict__ node,
                          const int* __restrict__ atoms,
                          float* __restrict__ out, int nCyc, int C, int pitch) {
    int idx = blockIdx.x * blockDim.x + threadIdx.x;
    if (idx >= nCyc * C) return;
    int i = idx / C;
    int c = idx - i * C;
    int base = i * G;
    float v[G];
    float bc = 0.f;
#pragma unroll
    for (int k = 0; k < G; k++) {
        int a = atoms[base + k];
        v[k] = node[(size_t)a * C + c];
        bc += v[k];
    }
#pragma unroll
    for (int k = 0; k < G; k++) {
        size_t o = (size_t)(base + k) * pitch;
        out[o + c] = v[k];
        out[o + C + c] = bc;
    }
}

__global__ void copy_off(const float* __restrict__ src, float* __restrict__ dst,
                         int rows, int pitch, int off) {
    int idx = blockIdx.x * blockDim.x + threadIdx.x;
    if (idx >= rows * 64) return;
    int r = idx >> 6;
    int c = idx & 63;
    dst[(size_t)r * pitch + off + c] = src[idx];
}

__global__ void gather_edge(const float* __restrict__ nodeS,
                            const int* __restrict__ atoms,
                            float* __restrict__ xE, int nE) {
    int idx = blockIdx.x * blockDim.x + threadIdx.x;
    if (idx >= nE * 320) return;
    int e = idx / 320;
    int c = idx - e * 320;
    int a0 = atoms[2 * e];
    int a1 = atoms[2 * e + 1];
    float v0 = nodeS[(size_t)a0 * 320 + c];
    float v1 = nodeS[(size_t)a1 * 320 + c];
    float bc = v0 + v1;
    size_t r0 = (size_t)(2 * e) * 704;
    size_t r1 = (size_t)(2 * e + 1) * 704;
    xE[r0 + 64 + c] = v0;
    xE[r0 + 384 + c] = bc;
    xE[r1 + 64 + c] = v1;
    xE[r1 + 384 + c] = bc;
}

__global__ void make_scaleshift(const float* __restrict__ sum_,
                                const float* __restrict__ sq_,
                                const float* __restrict__ g,
                                const float* __restrict__ b,
                                float* __restrict__ scale,
                                float* __restrict__ shift, int C, float invM) {
    int j = blockIdx.x * blockDim.x + threadIdx.x;
    if (j >= C) return;
    float m = sum_[j] * invM;
    float v = sq_[j] * invM - m * m;
    v = fmaxf(v, 0.f);
    float s = g[j] * rsqrtf(v + EPS);
    scale[j] = s;
    shift[j] = b[j] - m * s;
}

__global__ void bn_relu_out(const float* __restrict__ z,
                            const float* __restrict__ scale,
                            const float* __restrict__ shift,
                            float* __restrict__ out, size_t n, int C) {
    size_t idx = (size_t)blockIdx.x * blockDim.x + threadIdx.x;
    if (idx >= n) return;
    int c = (int)(idx % C);
    out[idx] = fmaxf(z[idx] * scale[c] + shift[c], 0.f);
}

// column sum/sumsq of C[M,N] (N threads/block, blocks stride rows)
__global__ void colstats(const float* __restrict__ C, int M, int N,
                         float* __restrict__ sum, float* __restrict__ sq) {
    int c = threadIdx.x;
    float s = 0.f, q = 0.f;
    for (int r = blockIdx.x; r < M; r += gridDim.x) {
        float v = C[(size_t)r * N + c];
        s += v;
        q += v * v;
    }
    atomicAdd(&sum[c], s);
    atomicAdd(&sq[c], q);
}

// ---------------------------------------------------------------------------
// tf32 wmma GEMM. A:[M,K] row-major (K%32==0), B:[K,BN] row-major,
// C:[M rounded up to 128, BN]. Single block-column (grid.x = 1), N == BN.
// Stores are UNGUARDED: C must be padded to a multiple of 128 rows.
// APPLY_IN: a' = relu(a*inScale[k]+inShift[k]) applied on A-tile load.
// tf32 conversion happens at smem store.
// ---------------------------------------------------------------------------
template <int BN_, int WN_, bool APPLY_IN>
__global__ void __launch_bounds__(256)
gemm_wmma(const float* __restrict__ A, const float* __restrict__ B,
          float* __restrict__ C, int M, int K,
          const float* __restrict__ inScale,
          const float* __restrict__ inShift) {
    constexpr int BM = 128;
    constexpr int BK = 32;
    constexpr int LDA = BK + 8;    // 40
    constexpr int LDB = BN_ + 8;
    constexpr int FN = WN_ / 16;

    __shared__ float As[BM * LDA];
    __shared__ float Bs[BK * LDB];

    const int tid = threadIdx.x;
    const int warpId = tid >> 5;
    const int warpM = warpId & 3;      // 4 warps along M
    const int warpN = warpId >> 2;     // 2 warps along N
    const int mBase = blockIdx.x * BM;
    const int wm0 = warpM * 32;
    const int wn0 = warpN * WN_;

    wmma::fragment<wmma::accumulator, 16, 16, 8, float> acc[2][FN];
#pragma unroll
    for (int i = 0; i < 2; i++)
#pragma unroll
        for (int j = 0; j < FN; j++) wmma::fill_fragment(acc[i][j], 0.f);

    for (int k0 = 0; k0 < K; k0 += BK) {
        // --- A tile: BM x BK, zero-pad OOB rows, optional BN+ReLU, cvt tf32
        for (int v = tid; v < BM * BK / 4; v += 256) {
            int row = v >> 3;
            int kc = (v & 7) << 2;
            int gr = mBase + row;
            float4 a = make_float4(0.f, 0.f, 0.f, 0.f);
            if (gr < M)
                a = *reinterpret_cast<const float4*>(
                    &A[(size_t)gr * K + k0 + kc]);
            if (APPLY_IN) {
                int kg = k0 + kc;
                a.x = fmaxf(a.x * inScale[kg + 0] + inShift[kg + 0], 0.f);
                a.y = fmaxf(a.y * inScale[kg + 1] + inShift[kg + 1], 0.f);
                a.z = fmaxf(a.z * inScale[kg + 2] + inShift[kg + 2], 0.f);
                a.w = fmaxf(a.w * inScale[kg + 3] + inShift[kg + 3], 0.f);
            }
            float* s = &As[row * LDA + kc];
            s[0] = wmma::__float_to_tf32(a.x);
            s[1] = wmma::__float_to_tf32(a.y);
            s[2] = wmma::__float_to_tf32(a.z);
            s[3] = wmma::__float_to_tf32(a.w);
        }
        // --- B tile: BK x BN (always fully in range)
        constexpr int B4 = BN_ / 4;
        for (int v = tid; v < BK * B4; v += 256) {
            int row = v / B4;
            int col = (v % B4) << 2;
            float4 b = *reinterpret_cast<const float4*>(
                &B[(size_t)(k0 + row) * BN_ + col]);
            float* s = &Bs[row * LDB + col];
            s[0] = wmma::__float_to_tf32(b.x);
            s[1] = wmma::__float_to_tf32(b.y);
            s[2] = wmma::__float_to_tf32(b.z);
            s[3] = wmma::__float_to_tf32(b.w);
        }
        __syncthreads();

#pragma unroll
        for (int kk = 0; kk < BK; kk += 8) {
            wmma::fragment<wmma::matrix_a, 16, 16, 8, wmma::precision::tf32,
                           wmma::row_major> af[2];
#pragma unroll
            for (int i = 0; i < 2; i++)
                wmma::load_matrix_sync(af[i], &As[(wm0 + i * 16) * LDA + kk],
                                       LDA);
            wmma::fragment<wmma::matrix_b, 16, 16, 8, wmma::precision::tf32,
                           wmma::row_major> bf[FN];
#pragma unroll
            for (int j = 0; j < FN; j++)
                wmma::load_matrix_sync(bf[j], &Bs[kk * LDB + wn0 + j * 16],
                                       LDB);
#pragma unroll
            for (int i = 0; i < 2; i++)
#pragma unroll
                for (int j = 0; j < FN; j++)
                    wmma::mma_sync(acc[i][j], af[i], bf[j], acc[i][j]);
        }
        __syncthreads();
    }

#pragma unroll
    for (int i = 0; i < 2; i++)
#pragma unroll
        for (int j = 0; j < FN; j++)
            wmma::store_matrix_sync(
                &C[(size_t)(mBase + wm0 + i * 16) * BN_ + wn0 + j * 16],
                acc[i][j], BN_, wmma::mem_row_major);
}

// ---------------------------------------------------------------------------
// Host orchestration
// ---------------------------------------------------------------------------
static inline int cdiv(int a, int b) { return (a + b - 1) / b; }

static float* sym_addr(const void* s) {
    void* p = nullptr;
    cudaGetSymbolAddress(&p, s);
    return (float*)p;
}

static void run_mlp(const float* X, int M, int K, const float* W1,
                    const float* g1, const float* b1, const float* W2,
                    const float* g2, const float* b2, float* h, float* z,
                    float* out, float* psum, float* psq, float* sc1,
                    float* sh1, float* sc2, float* sh2) {
    zero_kernel<<<1, 256>>>(psum, 128);
    zero_kernel<<<1, 256>>>(psq, 128);
    gemm_wmma<128, 64, false><<<cdiv(M, 128), 256>>>(X, W1, h, M, K, nullptr,
                                                     nullptr);
    colstats<<<512, 128>>>(h, M, 128, psum, psq);
    make_scaleshift<<<1, 128>>>(psum, psq, g1, b1, sc1, sh1, 128, 1.f / M);
    zero_kernel<<<1, 256>>>(psum, 128);
    zero_kernel<<<1, 256>>>(psq, 128);
    gemm_wmma<64, 32, true><<<cdiv(M, 128), 256>>>(h, W2, z, M, 128, sc1, sh1);
    colstats<<<512, 64>>>(z, M, 64, psum, psq);
    make_scaleshift<<<1, 64>>>(psum, psq, g2, b2, sc2, sh2, 64, 1.f / M);
    size_t n = (size_t)M * 64;
    bn_relu_out<<<(int)((n + 255) / 256), 256>>>(z, sc2, sh2, out, n, 64);
}

extern "C" void kernel_launch(void* const* d_in, const int* in_sizes, int n_in,
                              void* d_out, int out_size) {
    const float* edge_feats = (const float*)d_in[0];
    const float* c5_feats = (const float*)d_in[1];
    const float* c6_feats = (const float*)d_in[2];
    const int* e_atoms = (const int*)d_in[3];
    const int* c5_atoms = (const int*)d_in[4];
    const int* c6_atoms = (const int*)d_in[5];
    const float* eW1 = (const float*)d_in[6];
    const float* eg1 = (const float*)d_in[7];
    const float* eb1 = (const float*)d_in[8];
    const float* eW2 = (const float*)d_in[9];
    const float* eg2 = (const float*)d_in[10];
    const float* eb2 = (const float*)d_in[11];
    const float* cW1 = (const float*)d_in[12];
    const float* cg1 = (const float*)d_in[13];
    const float* cb1 = (const float*)d_in[14];
    const float* cW2 = (const float*)d_in[15];
    const float* cg2 = (const float*)d_in[16];
    const float* cb2 = (const float*)d_in[17];

    float* out_edge = (float*)d_out;
    float* out_c5 = out_edge + (size_t)E_ROWS * H;
    float* out_c6 = out_c5 + (size_t)C5_ROWS * H;

    float* node64 = sym_addr(g_node64);
    float* node128 = sym_addr(g_node128);
    float* nodeS = sym_addr(g_nodeS);
    float* tmp128 = sym_addr(g_tmp128);
    float* new5 = sym_addr(g_new5);
    float* new6 = sym_addr(g_new6);
    float* xE = sym_addr(g_xE);
    float* h = sym_addr(g_h);
    float* z = sym_addr(g_z);
    float* psum = sym_addr(g_sum);
    float* psq = sym_addr(g_sq);
    float* sc1 = sym_addr(g_scale1);
    float* sh1 = sym_addr(g_shift1);
    float* sc2 = sym_addr(g_scale2);
    float* sh2 = sym_addr(g_shift2);

    const int TB = 256;

    // --- node1 = segsum(edge_feats by edge_atoms), 64 ch ---
    zero_kernel<<<cdiv(NNODES * 64, TB), TB>>>(node64, (size_t)NNODES * 64);
    scatter_add4<<<cdiv(E_ROWS * 64 / 4, TB), TB>>>(edge_feats, e_atoms,
                                                    node64, E_ROWS, 64);

    // --- cycle5 chain ---
    gather_lb<5><<<cdiv(NC5 * 64, TB), TB>>>(node64, c5_atoms, tmp128, NC5, 64,
                                             128);
    zero_kernel<<<cdiv(NNODES * 128, TB), TB>>>(node128, (size_t)NNODES * 128);
    scatter_add4<<<cdiv(C5_ROWS * 128 / 4, TB), TB>>>(tmp128, c5_atoms,
                                                      node128, C5_ROWS, 128);
    gather_lb<5><<<cdiv(NC5 * 128, TB), TB>>>(node128, c5_atoms, new5, NC5,
                                              128, 320);
    copy_off<<<cdiv(C5_ROWS * 64, TB), TB>>>(c5_feats, new5, C5_ROWS, 320, 256);

    // --- cycle6 chain ---
    gather_lb<6><<<cdiv(NC6 * 64, TB), TB>>>(node64, c6_atoms, tmp128, NC6, 64,
                                             128);
    zero_kernel<<<cdiv(NNODES * 128, TB), TB>>>(node128, (size_t)NNODES * 128);
    scatter_add4<<<cdiv(C6_ROWS * 128 / 4, TB), TB>>>(tmp128, c6_atoms,
                                                      node128, C6_ROWS, 128);
    gather_lb<6><<<cdiv(NC6 * 128, TB), TB>>>(node128, c6_atoms, new6, NC6,
                                              128, 320);
    copy_off<<<cdiv(C6_ROWS * 64, TB), TB>>>(c6_feats, new6, C6_ROWS, 320, 256);

    // --- nodeS = segsum(new5) + segsum(new6), 320 ch ---
    zero_kernel<<<cdiv(NNODES * 320, TB), TB>>>(nodeS, (size_t)NNODES * 320);
    scatter_add4<<<cdiv(C5_ROWS * 320 / 4, TB), TB>>>(new5, c5_atoms, nodeS,
                                                      C5_ROWS, 320);
    scatter_add4<<<cdiv(C6_ROWS * 320 / 4, TB), TB>>>(new6, c6_atoms, nodeS,
                                                      C6_ROWS, 320);

    // --- edge MLP input ---
    gather_edge<<<cdiv(NE * 320, TB), TB>>>(nodeS, e_atoms, xE, NE);
    copy_off<<<cdiv(E_ROWS * 64, TB), TB>>>(edge_feats, xE, E_ROWS, 704, 0);

    // --- MLPs ---
    run_mlp(xE, E_ROWS, 704, eW1, eg1, eb1, eW2, eg2, eb2, h, z, out_edge,
            psum, psq, sc1, sh1, sc2, sh2);
    run_mlp(new5, C5_ROWS, 320, cW1, cg1, cb1, cW2, cg2, cb2, h, z, out_c5,
            psum, psq, sc1, sh1, sc2, sh2);
    run_mlp(new6, C6_ROWS, 320, cW1, cg1, cb1, cW2, cg2, cb2, h, z, out_c6,
            psum, psq, sc1, sh1, sc2, sh2);

    (void)in_sizes;
    (void)n_in;
    (void)out_size;
}

// round 4
// speedup vs baseline: 1.7478x; 1.7478x over previous
#include <cuda_runtime.h>
#include <cuda_bf16.h>
#include <cstdint>

// ---------------------------------------------------------------------------
// Problem constants
// ---------------------------------------------------------------------------
#define H 64
#define NNODES 40000
#define NE 60000
#define NC5 30000
#define NC6 25000
#define E_ROWS (2 * NE)      // 120000
#define C5_ROWS (5 * NC5)    // 150000
#define C6_ROWS (6 * NC6)    // 150000
#define EPS 1e-5f
#define PAD_ROWS 128         // GEMM stores are unguarded; pad scratch outputs

// ---------------------------------------------------------------------------
// Device scratch (static: no allocation allowed)
// ---------------------------------------------------------------------------
__device__ float g_node64[NNODES * 64];
__device__ float g_node128[NNODES * 128];
__device__ float g_nodeS[NNODES * 320];
__device__ float g_tmp128[C5_ROWS * 128];
__device__ float g_new5[C5_ROWS * 320];
__device__ float g_new6[C6_ROWS * 320];
__device__ float g_xE[E_ROWS * 704];
__device__ float g_h[(C5_ROWS + PAD_ROWS) * 128];   // GEMM1 out (padded)
__device__ float g_z[(C5_ROWS + PAD_ROWS) * 64];    // GEMM2 out (padded)
__device__ float g_wbuf[704 * 128];                 // tf32-rounded weights
__device__ float g_sum[128];
__device__ float g_sq[128];
__device__ float g_scale1[128];
__device__ float g_shift1[128];
__device__ float g_scale2[64];
__device__ float g_shift2[64];

// ---------------------------------------------------------------------------
// Helpers
// ---------------------------------------------------------------------------
__device__ __forceinline__ uint32_t smem_u32(const void* p) {
    uint32_t a;
    asm("{ .reg .u64 t; cvta.to.shared.u64 t, %1; cvt.u32.u64 %0, t; }"
        : "=r"(a) : "l"(p));
    return a;
}

// round fp32 to tf32 (round-to-nearest), result stored as fp32 bits
__device__ __forceinline__ float f2tf(float x) {
    uint32_t r;
    asm("cvt.rna.tf32.f32 %0, %1;" : "=r"(r) : "f"(x));
    return __uint_as_float(r);
}

__device__ __forceinline__ void cp16(uint32_t dst, const void* src, int nbytes) {
    asm volatile("cp.async.ca.shared.global [%0], [%1], 16, %2;"
                 :: "r"(dst), "l"(src), "r"(nbytes) : "memory");
}
__device__ __forceinline__ void cp_commit() {
    asm volatile("cp.async.commit_group;" ::: "memory");
}
__device__ __forceinline__ void cp_wait1() {
    asm volatile("cp.async.wait_group 1;" ::: "memory");
}

__device__ __forceinline__ void mma_tf32(float* d, const uint32_t* a,
                                         const uint32_t* b) {
    asm volatile(
        "mma.sync.aligned.m16n8k8.row.col.f32.tf32.tf32.f32 "
        "{%0,%1,%2,%3}, {%4,%5,%6,%7}, {%8,%9}, {%0,%1,%2,%3};"
        : "+f"(d[0]), "+f"(d[1]), "+f"(d[2]), "+f"(d[3])
        : "r"(a[0]), "r"(a[1]), "r"(a[2]), "r"(a[3]), "r"(b[0]), "r"(b[1]));
}

// ---------------------------------------------------------------------------
// tf32 mma.sync GEMM, cp.async double-buffered.
// A:[M,K] fp32 (pre-rounded to tf32), B:[K,BN] fp32 (pre-rounded), C:[Mpad,BN].
// K % 32 == 0. Grid = cdiv(M,128) CTAs of 256 threads (8 warps: 4 M x 2 N).
// C rows beyond M are written (deterministic garbage); C must be padded.
// ---------------------------------------------------------------------------
template <int BN>
__global__ void __launch_bounds__(256)
gemm_mma(const float* __restrict__ A, const float* __restrict__ B,
         float* __restrict__ C, int M, int K) {
    constexpr int BM = 128, BK = 32;
    constexpr int APAD = 36;            // floats/row: banks (4*qr+ql) distinct
    constexpr int BPAD = BN + 8;        // banks (8*k+n) distinct
    constexpr int ASZ = BM * APAD;
    constexpr int BSZ = BK * BPAD;
    constexpr int STG = ASZ + BSZ;
    constexpr int NT = BN / 16;         // n-tiles (8 cols) per warp

    extern __shared__ float sm[];
    const int tid = threadIdx.x;
    const int warp = tid >> 5, lane = tid & 31;
    const int qr = lane >> 2, ql = lane & 3;
    const int wm = warp >> 1, wn = warp & 1;
    const int mBase = blockIdx.x * BM;
    const uint32_t smBase = smem_u32(sm);

    auto issue = [&](int s, int k0) {
        const int so = s * STG;
        // A tile: 128 rows x 32 floats = 1024 x 16B ops
#pragma unroll
        for (int j = 0; j < 4; j++) {
            int i = tid + 256 * j;
            int row = i >> 3, ch = i & 7;
            int gr = mBase + row;
            bool ok = gr < M;
            const float* src = A + (size_t)(ok ? gr : 0) * K + k0 + ch * 4;
            uint32_t dst = smBase + (uint32_t)(so + row * APAD + ch * 4) * 4;
            cp16(dst, src, ok ? 16 : 0);
        }
        // B tile: 32 rows x BN floats
#pragma unroll
        for (int j = 0; j < BK * BN / 4 / 256; j++) {
            int i = tid + 256 * j;
            int row = i / (BN / 4), c = i % (BN / 4);
            const float* src = B + (size_t)(k0 + row) * BN + c * 4;
            uint32_t dst =
                smBase + (uint32_t)(so + ASZ + row * BPAD + c * 4) * 4;
            cp16(dst, src, 16);
        }
    };

    float acc[2][NT][4];
#pragma unroll
    for (int t = 0; t < 2; t++)
#pragma unroll
        for (int j = 0; j < NT; j++)
#pragma unroll
            for (int r = 0; r < 4; r++) acc[t][j][r] = 0.f;

    const int nCh = K / BK;
    issue(0, 0);
    cp_commit();

    for (int c = 0; c < nCh; c++) {
        if (c + 1 < nCh) issue((c + 1) & 1, (c + 1) * BK);
        cp_commit();
        cp_wait1();
        __syncthreads();

        const uint32_t* Asm =
            reinterpret_cast<const uint32_t*>(sm) + (c & 1) * STG;
        const uint32_t* Bsm = Asm + ASZ;
#pragma unroll
        for (int ks = 0; ks < 4; ks++) {
            const int k = ks * 8;
            uint32_t a[2][4];
#pragma unroll
            for (int t = 0; t < 2; t++) {
                const uint32_t* p =
                    Asm + (wm * 32 + t * 16 + qr) * APAD + k + ql;
                a[t][0] = p[0];
                a[t][1] = p[8 * APAD];
                a[t][2] = p[4];
                a[t][3] = p[8 * APAD + 4];
            }
            uint32_t b[NT][2];
#pragma unroll
            for (int j = 0; j < NT; j++) {
                const uint32_t* p =
                    Bsm + (k + ql) * BPAD + wn * (BN / 2) + j * 8 + qr;
                b[j][0] = p[0];
                b[j][1] = p[4 * BPAD];
            }
#pragma unroll
            for (int t = 0; t < 2; t++)
#pragma unroll
                for (int j = 0; j < NT; j++) mma_tf32(acc[t][j], a[t], b[j]);
        }
        __syncthreads();
    }

    // store (C padded; no M guard needed)
#pragma unroll
    for (int t = 0; t < 2; t++) {
        int r0 = mBase + wm * 32 + t * 16 + qr;
#pragma unroll
        for (int j = 0; j < NT; j++) {
            int n0 = wn * (BN / 2) + j * 8 + 2 * ql;
            *reinterpret_cast<float2*>(&C[(size_t)r0 * BN + n0]) =
                make_float2(acc[t][j][0], acc[t][j][1]);
            *reinterpret_cast<float2*>(&C[(size_t)(r0 + 8) * BN + n0]) =
                make_float2(acc[t][j][2], acc[t][j][3]);
        }
    }
}

// ---------------------------------------------------------------------------
// Memory-phase kernels
// ---------------------------------------------------------------------------
__global__ void zero_kernel(float* __restrict__ p, size_t n) {
    size_t i = (size_t)blockIdx.x * blockDim.x + threadIdx.x;
    if (i < n) p[i] = 0.f;
}

__global__ void scatter_add4(const float* __restrict__ src,
                             const int* __restrict__ atoms,
                             float* __restrict__ node, int rows, int C) {
    int C4 = C >> 2;
    int idx = blockIdx.x * blockDim.x + threadIdx.x;
    int total = rows * C4;
    if (idx >= total) return;
    int r = idx / C4;
    int c = (idx - r * C4) << 2;
    float4 v = *reinterpret_cast<const float4*>(&src[(size_t)r * C + c]);
    float* dst = &node[(size_t)atoms[r] * C + c];
    atomicAdd(dst + 0, v.x);
    atomicAdd(dst + 1, v.y);
    atomicAdd(dst + 2, v.z);
    atomicAdd(dst + 3, v.w);
}

// RND: round outputs to tf32 (for GEMM-input buffers)
template <int G, bool RND>
__global__ void gather_lb(const float* __restrict__ node,
                          const int* __restrict__ atoms,
                          float* __restrict__ out, int nCyc, int C, int pitch) {
    int idx = blockIdx.x * blockDim.x + threadIdx.x;
    if (idx >= nCyc * C) return;
    int i = idx / C;
    int c = idx - i * C;
    int base = i * G;
    float v[G];
    float bc = 0.f;
#pragma unroll
    for (int k = 0; k < G; k++) {
        int a = atoms[base + k];
        v[k] = node[(size_t)a * C + c];
        bc += v[k];
    }
    if (RND) bc = f2tf(bc);
#pragma unroll
    for (int k = 0; k < G; k++) {
        size_t o = (size_t)(base + k) * pitch;
        out[o + c] = RND ? f2tf(v[k]) : v[k];
        out[o + C + c] = bc;
    }
}

// copy 64-ch feats into dst[:, off:off+64] with row pitch, tf32-rounded
__global__ void copy_off(const float* __restrict__ src, float* __restrict__ dst,
                         int rows, int pitch, int off) {
    int idx = blockIdx.x * blockDim.x + threadIdx.x;
    if (idx >= rows * 64) return;
    int r = idx >> 6;
    int c = idx & 63;
    dst[(size_t)r * pitch + off + c] = f2tf(src[idx]);
}

__global__ void gather_edge(const float* __restrict__ nodeS,
                            const int* __restrict__ atoms,
                            float* __restrict__ xE, int nE) {
    int idx = blockIdx.x * blockDim.x + threadIdx.x;
    if (idx >= nE * 320) return;
    int e = idx / 320;
    int c = idx - e * 320;
    int a0 = atoms[2 * e];
    int a1 = atoms[2 * e + 1];
    float v0 = nodeS[(size_t)a0 * 320 + c];
    float v1 = nodeS[(size_t)a1 * 320 + c];
    float bc = f2tf(v0 + v1);
    size_t r0 = (size_t)(2 * e) * 704;
    size_t r1 = (size_t)(2 * e + 1) * 704;
    xE[r0 + 64 + c] = f2tf(v0);
    xE[r0 + 384 + c] = bc;
    xE[r1 + 64 + c] = f2tf(v1);
    xE[r1 + 384 + c] = bc;
}

__global__ void round_tf32(const float* __restrict__ src,
                           float* __restrict__ dst, int n) {
    int i = blockIdx.x * blockDim.x + threadIdx.x;
    if (i < n) dst[i] = f2tf(src[i]);
}

__global__ void make_scaleshift(const float* __restrict__ sum_,
                                const float* __restrict__ sq_,
                                const float* __restrict__ g,
                                const float* __restrict__ b,
                                float* __restrict__ scale,
                                float* __restrict__ shift, int C, float invM) {
    int j = blockIdx.x * blockDim.x + threadIdx.x;
    if (j >= C) return;
    float m = sum_[j] * invM;
    float v = sq_[j] * invM - m * m;
    v = fmaxf(v, 0.f);
    float s = g[j] * rsqrtf(v + EPS);
    scale[j] = s;
    shift[j] = b[j] - m * s;
}

// in-place BN + ReLU + tf32 round (prepares GEMM2 input)
__global__ void bn_relu_round_inplace(float* __restrict__ h,
                                      const float* __restrict__ scale,
                                      const float* __restrict__ shift,
                                      size_t n, int C) {
    size_t idx = (size_t)blockIdx.x * blockDim.x + threadIdx.x;
    if (idx >= n) return;
    int c = (int)(idx % C);
    h[idx] = f2tf(fmaxf(h[idx] * scale[c] + shift[c], 0.f));
}

__global__ void bn_relu_out(const float* __restrict__ z,
                            const float* __restrict__ scale,
                            const float* __restrict__ shift,
                            float* __restrict__ out, size_t n, int C) {
    size_t idx = (size_t)blockIdx.x * blockDim.x + threadIdx.x;
    if (idx >= n) return;
    int c = (int)(idx % C);
    out[idx] = fmaxf(z[idx] * scale[c] + shift[c], 0.f);
}

__global__ void colstats(const float* __restrict__ C, int M, int N,
                         float* __restrict__ sum, float* __restrict__ sq) {
    int c = threadIdx.x;
    float s = 0.f, q = 0.f;
    for (int r = blockIdx.x; r < M; r += gridDim.x) {
        float v = C[(size_t)r * N + c];
        s += v;
        q += v * v;
    }
    atomicAdd(&sum[c], s);
    atomicAdd(&sq[c], q);
}

// ---------------------------------------------------------------------------
// Host orchestration
// ---------------------------------------------------------------------------
static inline int cdiv(int a, int b) { return (a + b - 1) / b; }

static float* sym_addr(const void* s) {
    void* p = nullptr;
    cudaGetSymbolAddress(&p, s);
    return (float*)p;
}

static const int SMEM_G128 = 2 * (128 * 36 + 32 * 136) * 4;  // 71680
static const int SMEM_G64 = 2 * (128 * 36 + 32 * 72) * 4;    // 55296

static void run_mlp(const float* X, int M, int K, const float* W1,
                    const float* g1, const float* b1, const float* W2,
                    const float* g2, const float* b2, float* h, float* z,
                    float* wbuf, float* out, float* psum, float* psq,
                    float* sc1, float* sh1, float* sc2, float* sh2) {
    zero_kernel<<<1, 256>>>(psum, 128);
    zero_kernel<<<1, 256>>>(psq, 128);
    round_tf32<<<cdiv(K * 128, 256), 256>>>(W1, wbuf, K * 128);
    gemm_mma<128><<<cdiv(M, 128), 256, SMEM_G128>>>(X, wbuf, h, M, K);
    colstats<<<512, 128>>>(h, M, 128, psum, psq);
    make_scaleshift<<<1, 128>>>(psum, psq, g1, b1, sc1, sh1, 128, 1.f / M);
    size_t nh = (size_t)M * 128;
    bn_relu_round_inplace<<<(int)((nh + 255) / 256), 256>>>(h, sc1, sh1, nh,
                                                            128);
    zero_kernel<<<1, 256>>>(psum, 128);
    zero_kernel<<<1, 256>>>(psq, 128);
    round_tf32<<<cdiv(128 * 64, 256), 256>>>(W2, wbuf, 128 * 64);
    gemm_mma<64><<<cdiv(M, 128), 256, SMEM_G64>>>(h, wbuf, z, M, 128);
    colstats<<<512, 64>>>(z, M, 64, psum, psq);
    make_scaleshift<<<1, 64>>>(psum, psq, g2, b2, sc2, sh2, 64, 1.f / M);
    size_t n = (size_t)M * 64;
    bn_relu_out<<<(int)((n + 255) / 256), 256>>>(z, sc2, sh2, out, n, 64);
}

extern "C" void kernel_launch(void* const* d_in, const int* in_sizes, int n_in,
                              void* d_out, int out_size) {
    static bool attr_done = false;
    if (!attr_done) {
        cudaFuncSetAttribute(gemm_mma<128>,
                             cudaFuncAttributeMaxDynamicSharedMemorySize,
                             SMEM_G128);
        cudaFuncSetAttribute(gemm_mma<64>,
                             cudaFuncAttributeMaxDynamicSharedMemorySize,
                             SMEM_G64);
        attr_done = true;
    }

    const float* edge_feats = (const float*)d_in[0];
    const float* c5_feats = (const float*)d_in[1];
    const float* c6_feats = (const float*)d_in[2];
    const int* e_atoms = (const int*)d_in[3];
    const int* c5_atoms = (const int*)d_in[4];
    const int* c6_atoms = (const int*)d_in[5];
    const float* eW1 = (const float*)d_in[6];
    const float* eg1 = (const float*)d_in[7];
    const float* eb1 = (const float*)d_in[8];
    const float* eW2 = (const float*)d_in[9];
    const float* eg2 = (const float*)d_in[10];
    const float* eb2 = (const float*)d_in[11];
    const float* cW1 = (const float*)d_in[12];
    const float* cg1 = (const float*)d_in[13];
    const float* cb1 = (const float*)d_in[14];
    const float* cW2 = (const float*)d_in[15];
    const float* cg2 = (const float*)d_in[16];
    const float* cb2 = (const float*)d_in[17];

    float* out_edge = (float*)d_out;
    float* out_c5 = out_edge + (size_t)E_ROWS * H;
    float* out_c6 = out_c5 + (size_t)C5_ROWS * H;

    float* node64 = sym_addr(g_node64);
    float* node128 = sym_addr(g_node128);
    float* nodeS = sym_addr(g_nodeS);
    float* tmp128 = sym_addr(g_tmp128);
    float* new5 = sym_addr(g_new5);
    float* new6 = sym_addr(g_new6);
    float* xE = sym_addr(g_xE);
    float* h = sym_addr(g_h);
    float* z = sym_addr(g_z);
    float* wbuf = sym_addr(g_wbuf);
    float* psum = sym_addr(g_sum);
    float* psq = sym_addr(g_sq);
    float* sc1 = sym_addr(g_scale1);
    float* sh1 = sym_addr(g_shift1);
    float* sc2 = sym_addr(g_scale2);
    float* sh2 = sym_addr(g_shift2);

    const int TB = 256;

    zero_kernel<<<cdiv(NNODES * 64, TB), TB>>>(node64, (size_t)NNODES * 64);
    scatter_add4<<<cdiv(E_ROWS * 64 / 4, TB), TB>>>(edge_feats, e_atoms,
                                                    node64, E_ROWS, 64);

    gather_lb<5, false><<<cdiv(NC5 * 64, TB), TB>>>(node64, c5_atoms, tmp128,
                                                    NC5, 64, 128);
    zero_kernel<<<cdiv(NNODES * 128, TB), TB>>>(node128, (size_t)NNODES * 128);
    scatter_add4<<<cdiv(C5_ROWS * 128 / 4, TB), TB>>>(tmp128, c5_atoms,
                                                      node128, C5_ROWS, 128);
    gather_lb<5, true><<<cdiv(NC5 * 128, TB), TB>>>(node128, c5_atoms, new5,
                                                    NC5, 128, 320);
    copy_off<<<cdiv(C5_ROWS * 64, TB), TB>>>(c5_feats, new5, C5_ROWS, 320, 256);

    gather_lb<6, false><<<cdiv(NC6 * 64, TB), TB>>>(node64, c6_atoms, tmp128,
                                                    NC6, 64, 128);
    zero_kernel<<<cdiv(NNODES * 128, TB), TB>>>(node128, (size_t)NNODES * 128);
    scatter_add4<<<cdiv(C6_ROWS * 128 / 4, TB), TB>>>(tmp128, c6_atoms,
                                                      node128, C6_ROWS, 128);
    gather_lb<6, true><<<cdiv(NC6 * 128, TB), TB>>>(node128, c6_atoms, new6,
                                                    NC6, 128, 320);
    copy_off<<<cdiv(C6_ROWS * 64, TB), TB>>>(c6_feats, new6, C6_ROWS, 320, 256);

    zero_kernel<<<cdiv(NNODES * 320, TB), TB>>>(nodeS, (size_t)NNODES * 320);
    scatter_add4<<<cdiv(C5_ROWS * 320 / 4, TB), TB>>>(new5, c5_atoms, nodeS,
                                                      C5_ROWS, 320);
    scatter_add4<<<cdiv(C6_ROWS * 320 / 4, TB), TB>>>(new6, c6_atoms, nodeS,
                                                      C6_ROWS, 320);

    gather_edge<<<cdiv(NE * 320, TB), TB>>>(nodeS, e_atoms, xE, NE);
    copy_off<<<cdiv(E_ROWS * 64, TB), TB>>>(edge_feats, xE, E_ROWS, 704, 0);

    run_mlp(xE, E_ROWS, 704, eW1, eg1, eb1, eW2, eg2, eb2, h, z, wbuf,
            out_edge, psum, psq, sc1, sh1, sc2, sh2);
    run_mlp(new5, C5_ROWS, 320, cW1, cg1, cb1, cW2, cg2, cb2, h, z, wbuf,
            out_c5, psum, psq, sc1, sh1, sc2, sh2);
    run_mlp(new6, C6_ROWS, 320, cW1, cg1, cb1, cW2, cg2, cb2, h, z, wbuf,
            out_c6, psum, psq, sc1, sh1, sc2, sh2);

    (void)in_sizes;
    (void)n_in;
    (void)out_size;
}

// round 5
// speedup vs baseline: 3.2213x; 1.8430x over previous
#include <cuda_runtime.h>
#include <cuda_bf16.h>
#include <cstdint>

// ---------------------------------------------------------------------------
// Problem constants
// ---------------------------------------------------------------------------
#define H 64
#define NNODES 40000
#define NE 60000
#define NC5 30000
#define NC6 25000
#define E_ROWS (2 * NE)      // 120000
#define C5_ROWS (5 * NC5)    // 150000
#define C6_ROWS (6 * NC6)    // 150000
#define EPS 1e-5f

// padded row counts (GEMM stores are unguarded)
#define PAD_N  40064     // cdiv(40000,128)*128
#define PAD_R  30080     // cdiv(30000,128)*128
#define PAD_F  150016    // cdiv(150000,128)*128 (covers 120000 too)

// ---------------------------------------------------------------------------
// Device scratch (static: no allocation allowed)
// ---------------------------------------------------------------------------
__device__ float g_node64[NNODES * 64];
__device__ float g_cnt5[NNODES];
__device__ float g_cnt6[NNODES];
__device__ float g_b1_5[NC5 * 64];
__device__ float g_b1_6[NC6 * 64];
__device__ float g_n128_5[NNODES * 128];
__device__ float g_n128_6[NNODES * 128];
__device__ float g_b2_5[NC5 * 128];
__device__ float g_b2_6[NC6 * 128];
__device__ float g_nodeS[NNODES * 320];
__device__ float g_B[PAD_N * 128];     // nodeS @ eW1[64:384]
__device__ float g_Bm[PAD_N * 128];    // nodeS @ eW1[384:704]
__device__ float g_P[PAD_N * 128];     // node128 @ cW1[0:128]   (reused 5/6)
__device__ float g_R[PAD_R * 128];     // b2 @ cW1[128:256]      (reused 5/6)
__device__ float g_F[PAD_F * 128];     // feats @ W_top          (reused e/5/6)
__device__ float g_h[PAD_F * 128];     // pre-BN hidden          (reused)
__device__ float g_z[PAD_F * 64];      // pre-BN output          (reused)
__device__ float g_wE1[704 * 128];     // tf32-rounded weights
__device__ float g_wE2[128 * 64];
__device__ float g_wC1[320 * 128];
__device__ float g_wC2[128 * 64];
__device__ float g_sum[128];
__device__ float g_sq[128];
__device__ float g_scale1[128];
__device__ float g_shift1[128];
__device__ float g_scale2[64];
__device__ float g_shift2[64];

// ---------------------------------------------------------------------------
// Helpers
// ---------------------------------------------------------------------------
__device__ __forceinline__ uint32_t smem_u32(const void* p) {
    uint32_t a;
    asm("{ .reg .u64 t; cvta.to.shared.u64 t, %1; cvt.u32.u64 %0, t; }"
        : "=r"(a) : "l"(p));
    return a;
}

__device__ __forceinline__ float f2tf(float x) {
    uint32_t r;
    asm("cvt.rna.tf32.f32 %0, %1;" : "=r"(r) : "f"(x));
    return __uint_as_float(r);
}

__device__ __forceinline__ uint32_t f2tf_u(float x) {
    uint32_t r;
    asm("cvt.rna.tf32.f32 %0, %1;" : "=r"(r) : "f"(x));
    return r;
}

__device__ __forceinline__ void cp16(uint32_t dst, const void* src, int nbytes) {
    asm volatile("cp.async.ca.shared.global [%0], [%1], 16, %2;"
                 :: "r"(dst), "l"(src), "r"(nbytes) : "memory");
}
__device__ __forceinline__ void cp_commit() {
    asm volatile("cp.async.commit_group;" ::: "memory");
}
__device__ __forceinline__ void cp_wait1() {
    asm volatile("cp.async.wait_group 1;" ::: "memory");
}

__device__ __forceinline__ void mma_tf32(float* d, const uint32_t* a,
                                         const uint32_t* b) {
    asm volatile(
        "mma.sync.aligned.m16n8k8.row.col.f32.tf32.tf32.f32 "
        "{%0,%1,%2,%3}, {%4,%5,%6,%7}, {%8,%9}, {%0,%1,%2,%3};"
        : "+f"(d[0]), "+f"(d[1]), "+f"(d[2]), "+f"(d[3])
        : "r"(a[0]), "r"(a[1]), "r"(a[2]), "r"(a[3]), "r"(b[0]), "r"(b[1]));
}

// ---------------------------------------------------------------------------
// tf32 mma.sync GEMM, cp.async double-buffered.
// A:[M,K] raw fp32 (tf32-rounded in-register at fragment load),
// B:[K,BN] pre-rounded fp32, C:[Mpad,BN]. K % 32 == 0.
// APPLY_IN: a' = relu(a*inScale[k]+inShift[k]) fused (K<=128), then rounded.
// ---------------------------------------------------------------------------
template <int BN, bool APPLY_IN>
__global__ void __launch_bounds__(256)
gemm_mma(const float* __restrict__ A, const float* __restrict__ B,
         float* __restrict__ C, int M, int K,
         const float* __restrict__ inScale,
         const float* __restrict__ inShift) {
    constexpr int BM = 128, BK = 32;
    constexpr int APAD = 36;
    constexpr int BPAD = BN + 8;
    constexpr int ASZ = BM * APAD;
    constexpr int BSZ = BK * BPAD;
    constexpr int STG = ASZ + BSZ;
    constexpr int SOFF = 256;          // scale/shift region (floats)
    constexpr int NT = BN / 16;

    extern __shared__ float sm[];
    const int tid = threadIdx.x;
    const int warp = tid >> 5, lane = tid & 31;
    const int qr = lane >> 2, ql = lane & 3;
    const int wm = warp >> 1, wn = warp & 1;
    const int mBase = blockIdx.x * BM;
    const uint32_t smBase = smem_u32(sm);

    if (APPLY_IN && tid < 128) {
        sm[tid] = tid < K ? inScale[tid] : 0.f;
        sm[128 + tid] = tid < K ? inShift[tid] : 0.f;
    }

    auto issue = [&](int s, int k0) {
        const int so = SOFF + s * STG;
#pragma unroll
        for (int j = 0; j < 4; j++) {
            int i = tid + 256 * j;
            int row = i >> 3, ch = i & 7;
            int gr = mBase + row;
            bool ok = gr < M;
            const float* src = A + (size_t)(ok ? gr : 0) * K + k0 + ch * 4;
            uint32_t dst = smBase + (uint32_t)(so + row * APAD + ch * 4) * 4;
            cp16(dst, src, ok ? 16 : 0);
        }
#pragma unroll
        for (int j = 0; j < BK * BN / 4 / 256; j++) {
            int i = tid + 256 * j;
            int row = i / (BN / 4), c = i % (BN / 4);
            const float* src = B + (size_t)(k0 + row) * BN + c * 4;
            uint32_t dst =
                smBase + (uint32_t)(so + ASZ + row * BPAD + c * 4) * 4;
            cp16(dst, src, 16);
        }
    };

    float acc[2][NT][4];
#pragma unroll
    for (int t = 0; t < 2; t++)
#pragma unroll
        for (int j = 0; j < NT; j++)
#pragma unroll
            for (int r = 0; r < 4; r++) acc[t][j][r] = 0.f;

    const int nCh = K / BK;
    issue(0, 0);
    cp_commit();

    for (int c = 0; c < nCh; c++) {
        if (c + 1 < nCh) issue((c + 1) & 1, (c + 1) * BK);
        cp_commit();
        cp_wait1();
        __syncthreads();

        const float* Asm = sm + SOFF + (c & 1) * STG;
        const uint32_t* Bsm =
            reinterpret_cast<const uint32_t*>(Asm) + ASZ;
#pragma unroll
        for (int ks = 0; ks < 4; ks++) {
            const int k = ks * 8;
            float s0 = 1.f, h0 = 0.f, s4 = 1.f, h4 = 0.f;
            if (APPLY_IN) {
                int kc = c * 32 + k + ql;
                s0 = sm[kc];
                h0 = sm[128 + kc];
                s4 = sm[kc + 4];
                h4 = sm[128 + kc + 4];
            }
            uint32_t a[2][4];
#pragma unroll
            for (int t = 0; t < 2; t++) {
                const float* p = Asm + (wm * 32 + t * 16 + qr) * APAD + k + ql;
                float v0 = p[0], v1 = p[8 * APAD], v2 = p[4],
                      v3 = p[8 * APAD + 4];
                if (APPLY_IN) {
                    v0 = fmaxf(fmaf(v0, s0, h0), 0.f);
                    v1 = fmaxf(fmaf(v1, s0, h0), 0.f);
                    v2 = fmaxf(fmaf(v2, s4, h4), 0.f);
                    v3 = fmaxf(fmaf(v3, s4, h4), 0.f);
                }
                a[t][0] = f2tf_u(v0);
                a[t][1] = f2tf_u(v1);
                a[t][2] = f2tf_u(v2);
                a[t][3] = f2tf_u(v3);
            }
            uint32_t b[NT][2];
#pragma unroll
            for (int j = 0; j < NT; j++) {
                const uint32_t* p =
                    Bsm + (k + ql) * BPAD + wn * (BN / 2) + j * 8 + qr;
                b[j][0] = p[0];
                b[j][1] = p[4 * BPAD];
            }
#pragma unroll
            for (int t = 0; t < 2; t++)
#pragma unroll
                for (int j = 0; j < NT; j++) mma_tf32(acc[t][j], a[t], b[j]);
        }
        __syncthreads();
    }

#pragma unroll
    for (int t = 0; t < 2; t++) {
        int r0 = mBase + wm * 32 + t * 16 + qr;
#pragma unroll
        for (int j = 0; j < NT; j++) {
            int n0 = wn * (BN / 2) + j * 8 + 2 * ql;
            *reinterpret_cast<float2*>(&C[(size_t)r0 * BN + n0]) =
                make_float2(acc[t][j][0], acc[t][j][1]);
            *reinterpret_cast<float2*>(&C[(size_t)(r0 + 8) * BN + n0]) =
                make_float2(acc[t][j][2], acc[t][j][3]);
        }
    }
}

// ---------------------------------------------------------------------------
// Memory-phase kernels
// ---------------------------------------------------------------------------
__global__ void zero_kernel(float* __restrict__ p, size_t n) {
    size_t i = (size_t)blockIdx.x * blockDim.x + threadIdx.x;
    if (i < n) p[i] = 0.f;
}

__global__ void count_atoms(const int* __restrict__ atoms,
                            float* __restrict__ cnt, int rows) {
    int i = blockIdx.x * blockDim.x + threadIdx.x;
    if (i < rows) atomicAdd(&cnt[atoms[i]], 1.f);
}

// scatter-add rows of src[rows, C] into node[atoms[r]*pitch + off]
__global__ void scatter_add4(const float* __restrict__ src,
                             const int* __restrict__ atoms,
                             float* __restrict__ node, int rows, int C) {
    int C4 = C >> 2;
    int idx = blockIdx.x * blockDim.x + threadIdx.x;
    if (idx >= rows * C4) return;
    int r = idx / C4;
    int c = (idx - r * C4) << 2;
    float4 v = *reinterpret_cast<const float4*>(&src[(size_t)r * C + c]);
    float* dst = &node[(size_t)atoms[r] * C + c];
    atomicAdd(dst + 0, v.x);
    atomicAdd(dst + 1, v.y);
    atomicAdd(dst + 2, v.z);
    atomicAdd(dst + 3, v.w);
}

// per-group bc: out[i][c] = sum_{k<G} node[atoms[G*i+k]][c]
template <int G>
__global__ void bc_gather(const float* __restrict__ node,
                          const int* __restrict__ atoms,
                          float* __restrict__ out, int nCyc, int C) {
    int idx = blockIdx.x * blockDim.x + threadIdx.x;
    if (idx >= nCyc * C) return;
    int i = idx / C;
    int c = idx - i * C;
    float s = 0.f;
#pragma unroll
    for (int k = 0; k < G; k++) s += node[(size_t)atoms[i * G + k] * C + c];
    out[(size_t)i * C + c] = s;
}

// node128[a] = [cnt[a]*node64[a] | 0]
__global__ void init_node128(const float* __restrict__ node64,
                             const float* __restrict__ cnt,
                             float* __restrict__ node128) {
    int idx = blockIdx.x * blockDim.x + threadIdx.x;
    if (idx >= NNODES * 64) return;
    int a = idx >> 6, c = idx & 63;
    float s = cnt[a];
    node128[(size_t)a * 128 + c] = s * node64[(size_t)a * 64 + c];
    node128[(size_t)a * 128 + 64 + c] = 0.f;
}

// nodeS[a] = [cnt5*n5 + cnt6*n6 | 0 | 0]
__global__ void init_nodeS(const float* __restrict__ n5,
                           const float* __restrict__ n6,
                           const float* __restrict__ c5,
                           const float* __restrict__ c6,
                           float* __restrict__ nodeS) {
    int idx = blockIdx.x * blockDim.x + threadIdx.x;
    if (idx >= NNODES * 320) return;
    int a = idx / 320, c = idx - a * 320;
    float v = 0.f;
    if (c < 128)
        v = c5[a] * n5[(size_t)a * 128 + c] + c6[a] * n6[(size_t)a * 128 + c];
    nodeS[idx] = v;
}

// scatter with group-shared source row: dst[atoms[r]*pitch+off+c] += src[(r/G)*C+c]
template <int G>
__global__ void scatter_grp4(const float* __restrict__ src,
                             const int* __restrict__ atoms,
                             float* __restrict__ dst, int rows, int C,
                             int pitch, int off) {
    int C4 = C >> 2;
    int idx = blockIdx.x * blockDim.x + threadIdx.x;
    if (idx >= rows * C4) return;
    int r = idx / C4;
    int c = (idx - r * C4) << 2;
    float4 v =
        *reinterpret_cast<const float4*>(&src[(size_t)(r / G) * C + c]);
    float* d = &dst[(size_t)atoms[r] * pitch + off + c];
    atomicAdd(d + 0, v.x);
    atomicAdd(d + 1, v.y);
    atomicAdd(d + 2, v.z);
    atomicAdd(d + 3, v.w);
}

__global__ void round_tf32(const float* __restrict__ src,
                           float* __restrict__ dst, int n) {
    int i = blockIdx.x * blockDim.x + threadIdx.x;
    if (i < n) dst[i] = f2tf(src[i]);
}

// compose edge: h[r] = F[r] + B[self] + Bm[a0] + Bm[a1]; fused column stats
__global__ void compose_edge(const float* __restrict__ F,
                             const float* __restrict__ B,
                             const float* __restrict__ Bm,
                             const int* __restrict__ atoms,
                             float* __restrict__ h,
                             float* __restrict__ psum,
                             float* __restrict__ psq) {
    int c = threadIdx.x;  // 128
    float s = 0.f, q = 0.f;
    for (int r = blockIdx.x; r < E_ROWS; r += gridDim.x) {
        int e = r >> 1;
        int a0 = atoms[2 * e], a1 = atoms[2 * e + 1];
        int self = (r & 1) ? a1 : a0;
        float v = F[(size_t)r * 128 + c] + B[(size_t)self * 128 + c] +
                  Bm[(size_t)a0 * 128 + c] + Bm[(size_t)a1 * 128 + c];
        h[(size_t)r * 128 + c] = v;
        s += v;
        q += v * v;
    }
    atomicAdd(&psum[c], s);
    atomicAdd(&psq[c], q);
}

// compose cycle: h[r] = F[r] + P[atom[r]] + R[r/G]; fused column stats
template <int G>
__global__ void compose_cyc(const float* __restrict__ F,
                            const float* __restrict__ P,
                            const float* __restrict__ R,
                            const int* __restrict__ atoms,
                            float* __restrict__ h, int rows,
                            float* __restrict__ psum,
                            float* __restrict__ psq) {
    int c = threadIdx.x;  // 128
    float s = 0.f, q = 0.f;
    for (int r = blockIdx.x; r < rows; r += gridDim.x) {
        int a = atoms[r];
        float v = F[(size_t)r * 128 + c] + P[(size_t)a * 128 + c] +
                  R[(size_t)(r / G) * 128 + c];
        h[(size_t)r * 128 + c] = v;
        s += v;
        q += v * v;
    }
    atomicAdd(&psum[c], s);
    atomicAdd(&psq[c], q);
}

__global__ void make_scaleshift(const float* __restrict__ sum_,
                                const float* __restrict__ sq_,
                                const float* __restrict__ g,
                                const float* __restrict__ b,
                                float* __restrict__ scale,
                                float* __restrict__ shift, int C, float invM) {
    int j = blockIdx.x * blockDim.x + threadIdx.x;
    if (j >= C) return;
    float m = sum_[j] * invM;
    float v = sq_[j] * invM - m * m;
    v = fmaxf(v, 0.f);
    float s = g[j] * rsqrtf(v + EPS);
    scale[j] = s;
    shift[j] = b[j] - m * s;
}

__global__ void bn_relu_out(const float* __restrict__ z,
                            const float* __restrict__ scale,
                            const float* __restrict__ shift,
                            float* __restrict__ out, size_t n, int C) {
    size_t idx = (size_t)blockIdx.x * blockDim.x + threadIdx.x;
    if (idx >= n) return;
    int c = (int)(idx % C);
    out[idx] = fmaxf(z[idx] * scale[c] + shift[c], 0.f);
}

__global__ void colstats(const float* __restrict__ C, int M, int N,
                         float* __restrict__ sum, float* __restrict__ sq) {
    int c = threadIdx.x;
    float s = 0.f, q = 0.f;
    for (int r = blockIdx.x; r < M; r += gridDim.x) {
        float v = C[(size_t)r * N + c];
        s += v;
        q += v * v;
    }
    atomicAdd(&sum[c], s);
    atomicAdd(&sq[c], q);
}

// ---------------------------------------------------------------------------
// Host orchestration
// ---------------------------------------------------------------------------
static inline int cdiv(int a, int b) { return (a + b - 1) / b; }

static float* sym_addr(const void* s) {
    void* p = nullptr;
    cudaGetSymbolAddress(&p, s);
    return (float*)p;
}

static const int SMEM_G128 = (256 + 2 * (128 * 36 + 32 * 136)) * 4;  // 72704
static const int SMEM_G64 = (256 + 2 * (128 * 36 + 32 * 72)) * 4;    // 56320

extern "C" void kernel_launch(void* const* d_in, const int* in_sizes, int n_in,
                              void* d_out, int out_size) {
    static bool attr_done = false;
    if (!attr_done) {
        cudaFuncSetAttribute(gemm_mma<128, false>,
                             cudaFuncAttributeMaxDynamicSharedMemorySize,
                             SMEM_G128);
        cudaFuncSetAttribute(gemm_mma<64, true>,
                             cudaFuncAttributeMaxDynamicSharedMemorySize,
                             SMEM_G64);
        attr_done = true;
    }

    const float* edge_feats = (const float*)d_in[0];
    const float* c5_feats = (const float*)d_in[1];
    const float* c6_feats = (const float*)d_in[2];
    const int* e_atoms = (const int*)d_in[3];
    const int* c5_atoms = (const int*)d_in[4];
    const int* c6_atoms = (const int*)d_in[5];
    const float* eW1 = (const float*)d_in[6];
    const float* eg1 = (const float*)d_in[7];
    const float* eb1 = (const float*)d_in[8];
    const float* eW2 = (const float*)d_in[9];
    const float* eg2 = (const float*)d_in[10];
    const float* eb2 = (const float*)d_in[11];
    const float* cW1 = (const float*)d_in[12];
    const float* cg1 = (const float*)d_in[13];
    const float* cb1 = (const float*)d_in[14];
    const float* cW2 = (const float*)d_in[15];
    const float* cg2 = (const float*)d_in[16];
    const float* cb2 = (const float*)d_in[17];

    float* out_edge = (float*)d_out;
    float* out_c5 = out_edge + (size_t)E_ROWS * H;
    float* out_c6 = out_c5 + (size_t)C5_ROWS * H;

    float* node64 = sym_addr(g_node64);
    float* cnt5 = sym_addr(g_cnt5);
    float* cnt6 = sym_addr(g_cnt6);
    float* b1_5 = sym_addr(g_b1_5);
    float* b1_6 = sym_addr(g_b1_6);
    float* n128_5 = sym_addr(g_n128_5);
    float* n128_6 = sym_addr(g_n128_6);
    float* b2_5 = sym_addr(g_b2_5);
    float* b2_6 = sym_addr(g_b2_6);
    float* nodeS = sym_addr(g_nodeS);
    float* Bt = sym_addr(g_B);
    float* Bm = sym_addr(g_Bm);
    float* P = sym_addr(g_P);
    float* R = sym_addr(g_R);
    float* F = sym_addr(g_F);
    float* h = sym_addr(g_h);
    float* z = sym_addr(g_z);
    float* wE1 = sym_addr(g_wE1);
    float* wE2 = sym_addr(g_wE2);
    float* wC1 = sym_addr(g_wC1);
    float* wC2 = sym_addr(g_wC2);
    float* psum = sym_addr(g_sum);
    float* psq = sym_addr(g_sq);
    float* sc1 = sym_addr(g_scale1);
    float* sh1 = sym_addr(g_shift1);
    float* sc2 = sym_addr(g_scale2);
    float* sh2 = sym_addr(g_shift2);

    const int TB = 256;

    // ---- round weights once ----
    round_tf32<<<cdiv(704 * 128, TB), TB>>>(eW1, wE1, 704 * 128);
    round_tf32<<<cdiv(128 * 64, TB), TB>>>(eW2, wE2, 128 * 64);
    round_tf32<<<cdiv(320 * 128, TB), TB>>>(cW1, wC1, 320 * 128);
    round_tf32<<<cdiv(128 * 64, TB), TB>>>(cW2, wC2, 128 * 64);

    // ---- scatter chain (fp32 exact) ----
    zero_kernel<<<cdiv(NNODES * 64, TB), TB>>>(node64, (size_t)NNODES * 64);
    zero_kernel<<<cdiv(NNODES, TB), TB>>>(cnt5, NNODES);
    zero_kernel<<<cdiv(NNODES, TB), TB>>>(cnt6, NNODES);
    scatter_add4<<<cdiv(E_ROWS * 16, TB), TB>>>(edge_feats, e_atoms, node64,
                                                E_ROWS, 64);
    count_atoms<<<cdiv(C5_ROWS, TB), TB>>>(c5_atoms, cnt5, C5_ROWS);
    count_atoms<<<cdiv(C6_ROWS, TB), TB>>>(c6_atoms, cnt6, C6_ROWS);

    bc_gather<5><<<cdiv(NC5 * 64, TB), TB>>>(node64, c5_atoms, b1_5, NC5, 64);
    bc_gather<6><<<cdiv(NC6 * 64, TB), TB>>>(node64, c6_atoms, b1_6, NC6, 64);

    init_node128<<<cdiv(NNODES * 64, TB), TB>>>(node64, cnt5, n128_5);
    init_node128<<<cdiv(NNODES * 64, TB), TB>>>(node64, cnt6, n128_6);
    scatter_grp4<5><<<cdiv(C5_ROWS * 16, TB), TB>>>(b1_5, c5_atoms, n128_5,
                                                    C5_ROWS, 64, 128, 64);
    scatter_grp4<6><<<cdiv(C6_ROWS * 16, TB), TB>>>(b1_6, c6_atoms, n128_6,
                                                    C6_ROWS, 64, 128, 64);

    bc_gather<5><<<cdiv(NC5 * 128, TB), TB>>>(n128_5, c5_atoms, b2_5, NC5, 128);
    bc_gather<6><<<cdiv(NC6 * 128, TB), TB>>>(n128_6, c6_atoms, b2_6, NC6, 128);

    init_nodeS<<<cdiv(NNODES * 320, TB), TB>>>(n128_5, n128_6, cnt5, cnt6,
                                               nodeS);
    scatter_grp4<5><<<cdiv(C5_ROWS * 32, TB), TB>>>(b2_5, c5_atoms, nodeS,
                                                    C5_ROWS, 128, 320, 128);
    scatter_grp4<6><<<cdiv(C6_ROWS * 32, TB), TB>>>(b2_6, c6_atoms, nodeS,
                                                    C6_ROWS, 128, 320, 128);
    scatter_grp4<1><<<cdiv(C5_ROWS * 16, TB), TB>>>(c5_feats, c5_atoms, nodeS,
                                                    C5_ROWS, 64, 320, 256);
    scatter_grp4<1><<<cdiv(C6_ROWS * 16, TB), TB>>>(c6_feats, c6_atoms, nodeS,
                                                    C6_ROWS, 64, 320, 256);

    // ================= EDGE MLP =================
    gemm_mma<128, false><<<cdiv(E_ROWS, 128), 256, SMEM_G128>>>(
        edge_feats, wE1, F, E_ROWS, 64, nullptr, nullptr);
    gemm_mma<128, false><<<cdiv(NNODES, 128), 256, SMEM_G128>>>(
        nodeS, wE1 + 64 * 128, Bt, NNODES, 320, nullptr, nullptr);
    gemm_mma<128, false><<<cdiv(NNODES, 128), 256, SMEM_G128>>>(
        nodeS, wE1 + 384 * 128, Bm, NNODES, 320, nullptr, nullptr);
    zero_kernel<<<1, 256>>>(psum, 128);
    zero_kernel<<<1, 256>>>(psq, 128);
    compose_edge<<<2048, 128>>>(F, Bt, Bm, e_atoms, h, psum, psq);
    make_scaleshift<<<1, 128>>>(psum, psq, eg1, eb1, sc1, sh1, 128,
                                1.f / E_ROWS);
    gemm_mma<64, true><<<cdiv(E_ROWS, 128), 256, SMEM_G64>>>(
        h, wE2, z, E_ROWS, 128, sc1, sh1);
    zero_kernel<<<1, 256>>>(psum, 128);
    zero_kernel<<<1, 256>>>(psq, 128);
    colstats<<<1024, 64>>>(z, E_ROWS, 64, psum, psq);
    make_scaleshift<<<1, 64>>>(psum, psq, eg2, eb2, sc2, sh2, 64,
                               1.f / E_ROWS);
    bn_relu_out<<<cdiv(E_ROWS * 64, TB), TB>>>(z, sc2, sh2, out_edge,
                                               (size_t)E_ROWS * 64, 64);

    // ================= CYCLE5 MLP =================
    gemm_mma<128, false><<<cdiv(C5_ROWS, 128), 256, SMEM_G128>>>(
        c5_feats, wC1 + 256 * 128, F, C5_ROWS, 64, nullptr, nullptr);
    gemm_mma<128, false><<<cdiv(NNODES, 128), 256, SMEM_G128>>>(
        n128_5, wC1, P, NNODES, 128, nullptr, nullptr);
    gemm_mma<128, false><<<cdiv(NC5, 128), 256, SMEM_G128>>>(
        b2_5, wC1 + 128 * 128, R, NC5, 128, nullptr, nullptr);
    zero_kernel<<<1, 256>>>(psum, 128);
    zero_kernel<<<1, 256>>>(psq, 128);
    compose_cyc<5><<<2048, 128>>>(F, P, R, c5_atoms, h, C5_ROWS, psum, psq);
    make_scaleshift<<<1, 128>>>(psum, psq, cg1, cb1, sc1, sh1, 128,
                                1.f / C5_ROWS);
    gemm_mma<64, true><<<cdiv(C5_ROWS, 128), 256, SMEM_G64>>>(
        h, wC2, z, C5_ROWS, 128, sc1, sh1);
    zero_kernel<<<1, 256>>>(psum, 128);
    zero_kernel<<<1, 256>>>(psq, 128);
    colstats<<<1024, 64>>>(z, C5_ROWS, 64, psum, psq);
    make_scaleshift<<<1, 64>>>(psum, psq, cg2, cb2, sc2, sh2, 64,
                               1.f / C5_ROWS);
    bn_relu_out<<<cdiv(C5_ROWS * 64, TB), TB>>>(z, sc2, sh2, out_c5,
                                                (size_t)C5_ROWS * 64, 64);

    // ================= CYCLE6 MLP =================
    gemm_mma<128, false><<<cdiv(C6_ROWS, 128), 256, SMEM_G128>>>(
        c6_feats, wC1 + 256 * 128, F, C6_ROWS, 64, nullptr, nullptr);
    gemm_mma<128, false><<<cdiv(NNODES, 128), 256, SMEM_G128>>>(
        n128_6, wC1, P, NNODES, 128, nullptr, nullptr);
    gemm_mma<128, false><<<cdiv(NC6, 128), 256, SMEM_G128>>>(
        b2_6, wC1 + 128 * 128, R, NC6, 128, nullptr, nullptr);
    zero_kernel<<<1, 256>>>(psum, 128);
    zero_kernel<<<1, 256>>>(psq, 128);
    compose_cyc<6><<<2048, 128>>>(F, P, R, c6_atoms, h, C6_ROWS, psum, psq);
    make_scaleshift<<<1, 128>>>(psum, psq, cg1, cb1, sc1, sh1, 128,
                                1.f / C6_ROWS);
    gemm_mma<64, true><<<cdiv(C6_ROWS, 128), 256, SMEM_G64>>>(
        h, wC2, z, C6_ROWS, 128, sc1, sh1);
    zero_kernel<<<1, 256>>>(psum, 128);
    zero_kernel<<<1, 256>>>(psq, 128);
    colstats<<<1024, 64>>>(z, C6_ROWS, 64, psum, psq);
    make_scaleshift<<<1, 64>>>(psum, psq, cg2, cb2, sc2, sh2, 64,
                               1.f / C6_ROWS);
    bn_relu_out<<<cdiv(C6_ROWS * 64, TB), TB>>>(z, sc2, sh2, out_c6,
                                                (size_t)C6_ROWS * 64, 64);

    (void)in_sizes;
    (void)n_in;
    (void)out_size;
}